// round 1
// baseline (speedup 1.0000x reference)
#include <cuda_runtime.h>
#include <math.h>
#include <float.h>

#define BB 16
#define NN 4096
#define DD 1024
#define KK 1024
#define MM (NN - KK)   // 3072

// ---------------- device scratch (no allocations allowed) ----------------
__device__ int   g_kept_idx[BB * KK];
__device__ float g_kept_sc [BB * KK];
__device__ int   g_drop_idx[BB * MM];
__device__ float g_drop_sc [BB * MM];
__device__ float g_inv     [BB * NN];
__device__ int   g_assign  [BB * MM];
__device__ float g_sacc    [BB * KK];

// ---------------- helpers ----------------
__device__ __forceinline__ int block_excl_scan_1024(int val, int* wsum) {
    int tid = threadIdx.x;
    int lane = tid & 31, w = tid >> 5;
    __syncthreads();          // protect wsum reuse across calls
    int v = val;
#pragma unroll
    for (int off = 1; off < 32; off <<= 1) {
        int n = __shfl_up_sync(0xffffffffu, v, off);
        if (lane >= off) v += n;
    }
    if (lane == 31) wsum[w] = v;
    __syncthreads();
    if (w == 0) {
        int s = wsum[lane];
#pragma unroll
        for (int off = 1; off < 32; off <<= 1) {
            int n = __shfl_up_sync(0xffffffffu, s, off);
            if (lane >= off) s += n;
        }
        wsum[lane] = s;
    }
    __syncthreads();
    int base = (w ? wsum[w - 1] : 0);
    return base + v - val;    // exclusive prefix
}

// ---------------- K1: exact top-K select + index lists ----------------
// Histogram select on 4096 buckets (scores uniform in [0,1)), exact
// (value desc, index asc) tie-break inside the threshold bucket.
__global__ void __launch_bounds__(1024) topk_kernel(const float* __restrict__ scores,
                                                    float* __restrict__ out_idx,
                                                    float* __restrict__ out_sc,
                                                    int write_out)
{
    const int b   = blockIdx.x;
    const int tid = threadIdx.x;

    __shared__ float sh[NN];
    __shared__ int   hist[NN];
    __shared__ float tlv[1024];
    __shared__ int   tli[1024];
    __shared__ int   wsum[32];
    __shared__ int   s_t, s_C, s_nt;

    const float* sc = scores + (size_t)b * NN;
#pragma unroll
    for (int q = 0; q < 4; q++) {
        int i = tid * 4 + q;
        sh[i]   = sc[i];
        hist[i] = 0;
    }
    if (tid == 0) s_nt = 0;
    __syncthreads();

#pragma unroll
    for (int q = 0; q < 4; q++) {
        int i = tid * 4 + q;
        float s = sh[i];
        int bkt = (int)(s * (float)NN);
        bkt = max(0, min(NN - 1, bkt));
        atomicAdd(&hist[bkt], 1);
    }
    __syncthreads();

    // reversed exclusive scan over bins -> find threshold bucket
    int lc[4]; int cnt = 0;
#pragma unroll
    for (int q = 0; q < 4; q++) {
        lc[q] = hist[NN - 1 - (tid * 4 + q)];
        cnt += lc[q];
    }
    int base = block_excl_scan_1024(cnt, wsum);
    {
        int run = 0;
#pragma unroll
        for (int q = 0; q < 4; q++) {
            int rbin  = NN - 1 - (tid * 4 + q);
            int above = base + run;            // count in strictly higher buckets
            run += lc[q];
            if (above < KK && above + lc[q] >= KK) { s_t = rbin; s_C = above; }
        }
    }
    __syncthreads();
    const int tbkt = s_t, C = s_C, need = KK - C;

    // collect threshold-bucket elements
#pragma unroll
    for (int q = 0; q < 4; q++) {
        int i = tid * 4 + q;
        float s = sh[i];
        int bkt = max(0, min(NN - 1, (int)(s * (float)NN)));
        if (bkt == tbkt) {
            int p = atomicAdd(&s_nt, 1);
            if (p < 1024) { tlv[p] = s; tli[p] = i; }
        }
    }
    __syncthreads();
    const int nt = min(s_nt, 1024);

    // kept flags
    int kf[4]; int kcnt = 0;
#pragma unroll
    for (int q = 0; q < 4; q++) {
        int i = tid * 4 + q;
        float s = sh[i];
        int bkt = max(0, min(NN - 1, (int)(s * (float)NN)));
        int kept;
        if (bkt > tbkt)      kept = 1;
        else if (bkt < tbkt) kept = 0;
        else {
            int br = 0;
            for (int j = 0; j < nt; j++) {
                float ov = tlv[j]; int oi = tli[j];
                br += (ov > s) || (ov == s && oi < i);
            }
            kept = (br < need);
        }
        kf[q] = kept; kcnt += kept;
    }

    int kbase = block_excl_scan_1024(kcnt, wsum);
    int krun = 0;
#pragma unroll
    for (int q = 0; q < 4; q++) {
        int i = tid * 4 + q;
        float s = sh[i];
        if (kf[q]) {
            int kp = kbase + krun; krun++;
            g_kept_idx[b * KK + kp] = i;
            g_kept_sc [b * KK + kp] = s;
            if (write_out) {
                out_idx[b * KK + kp] = (float)i;
                out_sc [b * KK + kp] = s;
            }
        } else {
            int dp = i - (kbase + krun);
            g_drop_idx[b * MM + dp] = i;
            g_drop_sc [b * MM + dp] = s;
        }
    }
}

// ---------------- K2: inverse L2 norms for every token row ----------------
__global__ void norm_kernel(const float* __restrict__ tok)
{
    int w    = (blockIdx.x * blockDim.x + threadIdx.x) >> 5;
    int lane = threadIdx.x & 31;
    if (w >= BB * NN) return;
    const float4* p = (const float4*)(tok + (size_t)w * DD);
    float ss = 0.f;
#pragma unroll
    for (int i = 0; i < 8; i++) {
        float4 x = p[lane + 32 * i];
        ss += x.x * x.x + x.y * x.y + x.z * x.z + x.w * x.w;
    }
#pragma unroll
    for (int o = 16; o; o >>= 1) ss += __shfl_xor_sync(0xffffffffu, ss, o);
    if (!lane) g_inv[w] = 1.0f / fmaxf(sqrtf(ss), 1e-12f);
}

// ---------------- K2b: init output tokens = kept * k_sc; score accum = k_sc ----
__global__ void init_kernel(const float* __restrict__ tok, float* __restrict__ out_tok)
{
    int w    = (blockIdx.x * blockDim.x + threadIdx.x) >> 5;
    int lane = threadIdx.x & 31;
    if (w >= BB * KK) return;
    int b  = w >> 10;                 // KK = 1024
    int gi = g_kept_idx[w];
    float ksc = fmaxf(g_kept_sc[w], 0.0f);
    const float4* src = (const float4*)(tok + ((size_t)b * NN + gi) * DD);
    float4* dst = (float4*)(out_tok + (size_t)w * DD);
#pragma unroll
    for (int i = 0; i < 8; i++) {
        float4 x = src[lane + 32 * i];
        x.x *= ksc; x.y *= ksc; x.z *= ksc; x.w *= ksc;
        dst[lane + 32 * i] = x;
    }
    if (!lane) g_sacc[w] = ksc;
}

// ---------------- K3: fused fp32 GEMM (f32x2 FFMA) + row argmax ----------------
#define GBM 128
#define GBN 128
#define GBK 16
#define GAS (GBM + 4)   // padded stride, keeps 16B alignment (132*4=528)

__device__ __forceinline__ unsigned long long ffma2(unsigned long long a,
                                                    unsigned long long b,
                                                    unsigned long long c) {
    unsigned long long d;
    asm("fma.rn.f32x2 %0, %1, %2, %3;" : "=l"(d) : "l"(a), "l"(b), "l"(c));
    return d;
}
__device__ __forceinline__ unsigned long long pack2(float x) {
    unsigned long long d;
    asm("mov.b64 %0, {%1, %1};" : "=l"(d) : "f"(x));
    return d;
}
__device__ __forceinline__ float f2lo(unsigned long long a) { return __uint_as_float((unsigned)a); }
__device__ __forceinline__ float f2hi(unsigned long long a) { return __uint_as_float((unsigned)(a >> 32)); }

__global__ void __launch_bounds__(256) argmax_gemm_kernel(const float* __restrict__ tok)
{
    const int b   = blockIdx.y;
    const int m0  = blockIdx.x * GBM;
    const int tid = threadIdx.x;
    const int tx  = tid & 15, ty = tid >> 4;

    __shared__ float As[GBK][GAS];
    __shared__ float Bs[GBK][GAS];
    __shared__ int   s_arow[GBM];
    __shared__ float s_ainv[GBM];
    __shared__ int   s_brow[GBN];
    __shared__ float s_binv[GBN];

    if (tid < GBM) {
        int gi = g_drop_idx[b * MM + m0 + tid];
        s_arow[tid] = gi;
        s_ainv[tid] = g_inv[b * NN + gi];
    }

    float bestV[8]; int bestI[8];
#pragma unroll
    for (int r = 0; r < 8; r++) { bestV[r] = -FLT_MAX; bestI[r] = 0; }

    const float* tbase = tok + (size_t)b * NN * DD;

    for (int kt = 0; kt < KK / GBN; kt++) {
        const int k0 = kt * GBN;
        if (tid < GBN) {
            int gi = g_kept_idx[b * KK + k0 + tid];
            s_brow[tid] = gi;
            s_binv[tid] = g_inv[b * NN + gi];
        }
        __syncthreads();

        unsigned long long acc[8][4];
#pragma unroll
        for (int r = 0; r < 8; r++)
#pragma unroll
            for (int c = 0; c < 4; c++) acc[r][c] = 0ull;

        for (int d0 = 0; d0 < DD; d0 += GBK) {
#pragma unroll
            for (int t2 = 0; t2 < 2; t2++) {
                int idx = tid * 2 + t2;       // 0..511
                int mm_ = idx >> 2, q = idx & 3;
                float4 va = *(const float4*)(tbase + (size_t)s_arow[mm_] * DD + d0 + q * 4);
                float ia = s_ainv[mm_];
                As[q * 4 + 0][mm_] = va.x * ia;
                As[q * 4 + 1][mm_] = va.y * ia;
                As[q * 4 + 2][mm_] = va.z * ia;
                As[q * 4 + 3][mm_] = va.w * ia;
                float4 vb = *(const float4*)(tbase + (size_t)s_brow[mm_] * DD + d0 + q * 4);
                float ib = s_binv[mm_];
                Bs[q * 4 + 0][mm_] = vb.x * ib;
                Bs[q * 4 + 1][mm_] = vb.y * ib;
                Bs[q * 4 + 2][mm_] = vb.z * ib;
                Bs[q * 4 + 3][mm_] = vb.w * ib;
            }
            __syncthreads();
#pragma unroll
            for (int kk = 0; kk < GBK; kk++) {
                float4 a0 = *(const float4*)&As[kk][ty * 8];
                float4 a1 = *(const float4*)&As[kk][ty * 8 + 4];
                ulonglong2 b0 = *(const ulonglong2*)&Bs[kk][tx * 8];
                ulonglong2 b1 = *(const ulonglong2*)&Bs[kk][tx * 8 + 4];
                unsigned long long ap[8];
                ap[0] = pack2(a0.x); ap[1] = pack2(a0.y); ap[2] = pack2(a0.z); ap[3] = pack2(a0.w);
                ap[4] = pack2(a1.x); ap[5] = pack2(a1.y); ap[6] = pack2(a1.z); ap[7] = pack2(a1.w);
#pragma unroll
                for (int r = 0; r < 8; r++) {
                    acc[r][0] = ffma2(ap[r], b0.x, acc[r][0]);
                    acc[r][1] = ffma2(ap[r], b0.y, acc[r][1]);
                    acc[r][2] = ffma2(ap[r], b1.x, acc[r][2]);
                    acc[r][3] = ffma2(ap[r], b1.y, acc[r][3]);
                }
            }
            __syncthreads();
        }

        // fused argmax: first-max semantics (strict >, ties -> lower index)
#pragma unroll
        for (int r = 0; r < 8; r++) {
            float c[8];
            c[0] = f2lo(acc[r][0]); c[1] = f2hi(acc[r][0]);
            c[2] = f2lo(acc[r][1]); c[3] = f2hi(acc[r][1]);
            c[4] = f2lo(acc[r][2]); c[5] = f2hi(acc[r][2]);
            c[6] = f2lo(acc[r][3]); c[7] = f2hi(acc[r][3]);
            float lbv = c[0]; int lbi = tx * 8;
#pragma unroll
            for (int j = 1; j < 8; j++)
                if (c[j] > lbv) { lbv = c[j]; lbi = tx * 8 + j; }
#pragma unroll
            for (int off = 1; off < 16; off <<= 1) {
                float ov = __shfl_xor_sync(0xffffffffu, lbv, off, 16);
                int   oi = __shfl_xor_sync(0xffffffffu, lbi, off, 16);
                if (ov > lbv || (ov == lbv && oi < lbi)) { lbv = ov; lbi = oi; }
            }
            int gidx = k0 + lbi;
            if (lbv > bestV[r]) { bestV[r] = lbv; bestI[r] = gidx; }
        }
    }

    if (tx == 0) {
#pragma unroll
        for (int r = 0; r < 8; r++)
            g_assign[b * MM + m0 + ty * 8 + r] = bestI[r];
    }
}

// ---------------- K4: scatter-add weighted dropped tokens ----------------
__global__ void scatter_kernel(const float* __restrict__ tok, float* __restrict__ out_tok)
{
    int w    = (blockIdx.x * blockDim.x + threadIdx.x) >> 5;
    int lane = threadIdx.x & 31;
    if (w >= BB * MM) return;
    int b = w / MM;
    int a = g_assign[w];
    int gi = g_drop_idx[w];
    float dsc = fmaxf(g_drop_sc[w], 0.0f);
    const float4* src = (const float4*)(tok + ((size_t)b * NN + gi) * DD);
    float* dst = out_tok + ((size_t)b * KK + a) * DD;
#pragma unroll
    for (int i = 0; i < 8; i++) {
        float4 x = src[lane + 32 * i];
        int o = (lane + 32 * i) * 4;
        atomicAdd(dst + o + 0, x.x * dsc);
        atomicAdd(dst + o + 1, x.y * dsc);
        atomicAdd(dst + o + 2, x.z * dsc);
        atomicAdd(dst + o + 3, x.w * dsc);
    }
    if (!lane) atomicAdd(&g_sacc[b * KK + a], dsc);
}

// ---------------- K5: divide by denom in place ----------------
__global__ void final_kernel(float* __restrict__ out_tok)
{
    int w    = (blockIdx.x * blockDim.x + threadIdx.x) >> 5;
    int lane = threadIdx.x & 31;
    if (w >= BB * KK) return;
    float denom = fmaxf(g_sacc[w], 1e-6f);
    float4* p = (float4*)(out_tok + (size_t)w * DD);
#pragma unroll
    for (int i = 0; i < 8; i++) {
        float4 x = p[lane + 32 * i];
        x.x /= denom; x.y /= denom; x.z /= denom; x.w /= denom;
        p[lane + 32 * i] = x;
    }
}

// ---------------- entry ----------------
extern "C" void kernel_launch(void* const* d_in, const int* in_sizes, int n_in,
                              void* d_out, int out_size)
{
    const float* tok    = (const float*)d_in[0];   // [B,N,D] f32
    const float* scores = (const float*)d_in[1];   // [B,N]   f32
    float* out = (float*)d_out;

    float* out_tok = out;                                   // [B,K,D]
    int write_extra = (out_size >= BB * KK * DD + 2 * BB * KK);
    float* out_idx = out + (size_t)BB * KK * DD;            // [B,K] indices (as float)
    float* out_sc  = out_idx + BB * KK;                     // [B,K] scores

    topk_kernel<<<BB, 1024>>>(scores, out_idx, out_sc, write_extra);
    norm_kernel<<<(BB * NN) / 8, 256>>>(tok);
    init_kernel<<<(BB * KK) / 8, 256>>>(tok, out_tok);
    dim3 g(MM / GBM, BB);
    argmax_gemm_kernel<<<g, 256>>>(tok);
    scatter_kernel<<<(BB * MM) / 8, 256>>>(tok, out_tok);
    final_kernel<<<(BB * KK) / 8, 256>>>(out_tok);
}

// round 3
// speedup vs baseline: 1.8312x; 1.8312x over previous
#include <cuda_runtime.h>
#include <cuda_bf16.h>
#include <math.h>
#include <float.h>
#include <stdint.h>

#define BB 16
#define NN 4096
#define DD 1024
#define KK 1024
#define MM (NN - KK)   // 3072

// ---------------- device scratch (no allocations allowed) ----------------
__device__ int   g_kept_idx[BB * KK];
__device__ float g_kept_sc [BB * KK];
__device__ int   g_drop_idx[BB * MM];
__device__ float g_drop_sc [BB * MM];
__device__ float g_sacc    [BB * KK];
__device__ unsigned long long g_amax[BB * MM];   // packed (orderfloat<<32 | ~col)

// bf16 hi/lo split of normalized gathered rows (packed by kept/dropped position)
__device__ __align__(16) __nv_bfloat16 g_Dh[(size_t)BB * MM * DD];
__device__ __align__(16) __nv_bfloat16 g_Dl[(size_t)BB * MM * DD];
__device__ __align__(16) __nv_bfloat16 g_Kh[(size_t)BB * KK * DD];
__device__ __align__(16) __nv_bfloat16 g_Kl[(size_t)BB * KK * DD];

// ---------------- PTX helpers ----------------
__device__ __forceinline__ uint32_t smem_u32(const void* p) {
    uint32_t a;
    asm("{ .reg .u64 t; cvta.to.shared.u64 t, %1; cvt.u32.u64 %0, t; }" : "=r"(a) : "l"(p));
    return a;
}
__device__ __forceinline__ void cp16(uint32_t dst, const void* src) {
    asm volatile("cp.async.cg.shared.global [%0], [%1], 16;" :: "r"(dst), "l"(src));
}
#define CP_COMMIT() asm volatile("cp.async.commit_group;" ::: "memory")
#define CP_WAIT1()  asm volatile("cp.async.wait_group 1;" ::: "memory")
#define CP_WAIT0()  asm volatile("cp.async.wait_group 0;" ::: "memory")

__device__ __forceinline__ void ldsm_x4(uint32_t* r, uint32_t addr) {
    asm volatile("ldmatrix.sync.aligned.m8n8.x4.shared.b16 {%0,%1,%2,%3}, [%4];"
        : "=r"(r[0]), "=r"(r[1]), "=r"(r[2]), "=r"(r[3]) : "r"(addr));
}
__device__ __forceinline__ void mma16816(float* c, const uint32_t* a, uint32_t b0, uint32_t b1) {
    asm volatile(
        "mma.sync.aligned.m16n8k16.row.col.f32.bf16.bf16.f32 "
        "{%0,%1,%2,%3}, {%4,%5,%6,%7}, {%8,%9}, {%0,%1,%2,%3};"
        : "+f"(c[0]), "+f"(c[1]), "+f"(c[2]), "+f"(c[3])
        : "r"(a[0]), "r"(a[1]), "r"(a[2]), "r"(a[3]), "r"(b0), "r"(b1));
}
__device__ __forceinline__ unsigned long long shfl_xor_u64(unsigned long long x, int m) {
    uint32_t lo = (uint32_t)x, hi = (uint32_t)(x >> 32);
    lo = __shfl_xor_sync(0xffffffffu, lo, m);
    hi = __shfl_xor_sync(0xffffffffu, hi, m);
    return ((unsigned long long)hi << 32) | lo;
}

// ---------------- block scan helper ----------------
__device__ __forceinline__ int block_excl_scan_1024(int val, int* wsum) {
    int tid = threadIdx.x;
    int lane = tid & 31, w = tid >> 5;
    __syncthreads();
    int v = val;
#pragma unroll
    for (int off = 1; off < 32; off <<= 1) {
        int n = __shfl_up_sync(0xffffffffu, v, off);
        if (lane >= off) v += n;
    }
    if (lane == 31) wsum[w] = v;
    __syncthreads();
    if (w == 0) {
        int s = wsum[lane];
#pragma unroll
        for (int off = 1; off < 32; off <<= 1) {
            int n = __shfl_up_sync(0xffffffffu, s, off);
            if (lane >= off) s += n;
        }
        wsum[lane] = s;
    }
    __syncthreads();
    int base = (w ? wsum[w - 1] : 0);
    return base + v - val;
}

// ---------------- K1: exact top-K select (value desc, index asc ties) ------
__global__ void __launch_bounds__(1024) topk_kernel(const float* __restrict__ scores,
                                                    float* __restrict__ out_idx,
                                                    float* __restrict__ out_sc,
                                                    int write_out)
{
    const int b   = blockIdx.x;
    const int tid = threadIdx.x;

    __shared__ float sh[NN];
    __shared__ int   hist[NN];
    __shared__ float tlv[1024];
    __shared__ int   tli[1024];
    __shared__ int   wsum[32];
    __shared__ int   s_t, s_C, s_nt;

    const float* sc = scores + (size_t)b * NN;
#pragma unroll
    for (int q = 0; q < 4; q++) {
        int i = tid * 4 + q;
        sh[i]   = sc[i];
        hist[i] = 0;
    }
    if (tid == 0) s_nt = 0;
    __syncthreads();

#pragma unroll
    for (int q = 0; q < 4; q++) {
        int i = tid * 4 + q;
        float s = sh[i];
        int bkt = (int)(s * (float)NN);
        bkt = max(0, min(NN - 1, bkt));
        atomicAdd(&hist[bkt], 1);
    }
    __syncthreads();

    int lc[4]; int cnt = 0;
#pragma unroll
    for (int q = 0; q < 4; q++) {
        lc[q] = hist[NN - 1 - (tid * 4 + q)];
        cnt += lc[q];
    }
    int base = block_excl_scan_1024(cnt, wsum);
    {
        int run = 0;
#pragma unroll
        for (int q = 0; q < 4; q++) {
            int rbin  = NN - 1 - (tid * 4 + q);
            int above = base + run;
            run += lc[q];
            if (above < KK && above + lc[q] >= KK) { s_t = rbin; s_C = above; }
        }
    }
    __syncthreads();
    const int tbkt = s_t, C = s_C, need = KK - C;

#pragma unroll
    for (int q = 0; q < 4; q++) {
        int i = tid * 4 + q;
        float s = sh[i];
        int bkt = max(0, min(NN - 1, (int)(s * (float)NN)));
        if (bkt == tbkt) {
            int p = atomicAdd(&s_nt, 1);
            if (p < 1024) { tlv[p] = s; tli[p] = i; }
        }
    }
    __syncthreads();
    const int nt = min(s_nt, 1024);

    int kf[4]; int kcnt = 0;
#pragma unroll
    for (int q = 0; q < 4; q++) {
        int i = tid * 4 + q;
        float s = sh[i];
        int bkt = max(0, min(NN - 1, (int)(s * (float)NN)));
        int kept;
        if (bkt > tbkt)      kept = 1;
        else if (bkt < tbkt) kept = 0;
        else {
            int br = 0;
            for (int j = 0; j < nt; j++) {
                float ov = tlv[j]; int oi = tli[j];
                br += (ov > s) || (ov == s && oi < i);
            }
            kept = (br < need);
        }
        kf[q] = kept; kcnt += kept;
    }

    int kbase = block_excl_scan_1024(kcnt, wsum);
    int krun = 0;
#pragma unroll
    for (int q = 0; q < 4; q++) {
        int i = tid * 4 + q;
        float s = sh[i];
        if (kf[q]) {
            int kp = kbase + krun; krun++;
            g_kept_idx[b * KK + kp] = i;
            g_kept_sc [b * KK + kp] = s;
            if (write_out) {
                out_idx[b * KK + kp] = (float)i;
                out_sc [b * KK + kp] = s;
            }
        } else {
            int dp = i - (kbase + krun);
            g_drop_idx[b * MM + dp] = i;
            g_drop_sc [b * MM + dp] = s;
        }
    }
}

// ---------------- K2: gather + normalize + bf16 hi/lo split ----------------
__global__ void prep_kernel(const float* __restrict__ tok)
{
    int w    = (blockIdx.x * blockDim.x + threadIdx.x) >> 5;
    int lane = threadIdx.x & 31;
    if (w >= BB * NN) return;

    if (lane == 0 && w < BB * MM) g_amax[w] = 0ull;

    int b, gi;
    __nv_bfloat16 *dh, *dl;
    const int half = BB * KK;
    if (w < half) {
        b  = w >> 10;
        gi = g_kept_idx[w];
        dh = g_Kh + (size_t)w * DD;
        dl = g_Kl + (size_t)w * DD;
    } else {
        int w2 = w - half;
        b  = w2 / MM;
        gi = g_drop_idx[w2];
        dh = g_Dh + (size_t)w2 * DD;
        dl = g_Dl + (size_t)w2 * DD;
    }

    const float4* src = (const float4*)(tok + ((size_t)b * NN + gi) * DD);
    float4 x[8];
    float ss = 0.f;
#pragma unroll
    for (int i = 0; i < 8; i++) {
        x[i] = src[lane + 32 * i];
        ss += x[i].x * x[i].x + x[i].y * x[i].y + x[i].z * x[i].z + x[i].w * x[i].w;
    }
#pragma unroll
    for (int o = 16; o; o >>= 1) ss += __shfl_xor_sync(0xffffffffu, ss, o);
    float inv = 1.0f / fmaxf(sqrtf(ss), 1e-12f);

#pragma unroll
    for (int i = 0; i < 8; i++) {
        float v[4] = { x[i].x * inv, x[i].y * inv, x[i].z * inv, x[i].w * inv };
        __nv_bfloat16 h[4], l[4];
#pragma unroll
        for (int q = 0; q < 4; q++) {
            h[q] = __float2bfloat16(v[q]);
            l[q] = __float2bfloat16(v[q] - __bfloat162float(h[q]));
        }
        int e = (lane + 32 * i) * 4;
        *(__nv_bfloat162*)(dh + e)     = __nv_bfloat162(h[0], h[1]);
        *(__nv_bfloat162*)(dh + e + 2) = __nv_bfloat162(h[2], h[3]);
        *(__nv_bfloat162*)(dl + e)     = __nv_bfloat162(l[0], l[1]);
        *(__nv_bfloat162*)(dl + e + 2) = __nv_bfloat162(l[2], l[3]);
    }
}

// ---------------- K2b: init output tokens = kept * k_sc ----------------
__global__ void init_kernel(const float* __restrict__ tok, float* __restrict__ out_tok)
{
    int w    = (blockIdx.x * blockDim.x + threadIdx.x) >> 5;
    int lane = threadIdx.x & 31;
    if (w >= BB * KK) return;
    int b  = w >> 10;
    int gi = g_kept_idx[w];
    float ksc = fmaxf(g_kept_sc[w], 0.0f);
    const float4* src = (const float4*)(tok + ((size_t)b * NN + gi) * DD);
    float4* dst = (float4*)(out_tok + (size_t)w * DD);
#pragma unroll
    for (int i = 0; i < 8; i++) {
        float4 x = src[lane + 32 * i];
        x.x *= ksc; x.y *= ksc; x.z *= ksc; x.w *= ksc;
        dst[lane + 32 * i] = x;
    }
    if (!lane) g_sacc[w] = ksc;
}

// ---------------- K3: bf16 mma.sync GEMM (4-term split) + global argmax ----
// CTA tile 128(M) x 128(N); grid (24, 8, 16). K' = 4*1024 via segment select.
// SMEM rows: 32 bf16 (64B) padded to stride 40 bf16 (80B) -> ldmatrix
// 8-row phases hit all 32 banks (r*20 mod 32 covers 0..31 in 4-word groups).
#define KC 32
#define ROWB 80
#define BUFE (128 * 40)          // elements per buffer

__global__ void __launch_bounds__(256, 2) mma_argmax_kernel()
{
    __shared__ __align__(1024) __nv_bfloat16 As[2][BUFE];
    __shared__ __align__(1024) __nv_bfloat16 Bs[2][BUFE];

    const int b    = blockIdx.z;
    const int m0   = blockIdx.x * 128;
    const int n0   = blockIdx.y * 128;
    const int tid  = threadIdx.x;
    const int lane = tid & 31;
    const int wid  = tid >> 5;
    const int wm   = wid & 3;       // 4 warps along M (32 rows each)
    const int wn   = wid >> 2;      // 2 warps along N (64 cols each)

    const __nv_bfloat16* Ah = g_Dh + ((size_t)b * MM + m0) * DD;
    const __nv_bfloat16* Al = g_Dl + ((size_t)b * MM + m0) * DD;
    const __nv_bfloat16* Bh = g_Kh + ((size_t)b * KK + n0) * DD;
    const __nv_bfloat16* Bl = g_Kl + ((size_t)b * KK + n0) * DD;

    const uint32_t aBase = smem_u32(As);
    const uint32_t bBase = smem_u32(Bs);

    // load mapping: thread -> (row = tid>>1, 32-byte half = tid&1)
    const int lrow = tid >> 1;
    const int lh   = (tid & 1) * 32;

    float acc[2][8][4];
#pragma unroll
    for (int mi = 0; mi < 2; mi++)
#pragma unroll
        for (int ni = 0; ni < 8; ni++)
#pragma unroll
            for (int j = 0; j < 4; j++) acc[mi][ni][j] = 0.f;

    // ldmatrix address components (constant per thread)
    const uint32_t aRow  = (uint32_t)(wm * 32 + (lane & 15));
    const uint32_t aByte = (uint32_t)(((lane & 16) ? 16 : 0));
    const uint32_t bRow  = (uint32_t)(wn * 64 + (lane & 7) + ((lane & 16) ? 8 : 0));
    const uint32_t bByte = (uint32_t)(((lane & 8) ? 16 : 0));

    // issue loads for chunk c into buffer buf
    auto issue = [&](int c, int buf) {
        const int seg = c >> 5;
        const int d0  = (c & 31) * KC;
        const __nv_bfloat16* Aseg = (seg >= 2) ? Al : Ah;
        const __nv_bfloat16* Bseg = (seg & 1)  ? Bl : Bh;
        const char* ga = (const char*)(Aseg + (size_t)lrow * DD + d0) + lh;
        const char* gb = (const char*)(Bseg + (size_t)lrow * DD + d0) + lh;
        uint32_t da = aBase + (uint32_t)(buf * (BUFE * 2) + lrow * ROWB + lh);
        uint32_t db = bBase + (uint32_t)(buf * (BUFE * 2) + lrow * ROWB + lh);
        cp16(da,      ga);
        cp16(da + 16, ga + 16);
        cp16(db,      gb);
        cp16(db + 16, gb + 16);
    };

    issue(0, 0);
    CP_COMMIT();

    for (int c = 0; c < 128; c++) {
        const int buf = c & 1;
        if (c + 1 < 128) {
            issue(c + 1, buf ^ 1);
            CP_COMMIT();
            CP_WAIT1();
        } else {
            CP_WAIT0();
        }
        __syncthreads();

        const uint32_t aB = aBase + (uint32_t)(buf * (BUFE * 2));
        const uint32_t bB = bBase + (uint32_t)(buf * (BUFE * 2));
#pragma unroll
        for (int s = 0; s < 2; s++) {
            uint32_t afr[2][4];
#pragma unroll
            for (int mi = 0; mi < 2; mi++)
                ldsm_x4(afr[mi], aB + (aRow + mi * 16) * ROWB + s * 32 + aByte);
            uint32_t bfr[4][4];
#pragma unroll
            for (int np = 0; np < 4; np++)
                ldsm_x4(bfr[np], bB + (bRow + np * 16) * ROWB + s * 32 + bByte);
#pragma unroll
            for (int mi = 0; mi < 2; mi++)
#pragma unroll
                for (int ni = 0; ni < 8; ni++) {
                    const uint32_t* bp = &bfr[ni >> 1][(ni & 1) * 2];
                    mma16816(acc[mi][ni], afr[mi], bp[0], bp[1]);
                }
        }
        __syncthreads();
    }

    // epilogue: per-thread rows -> quad reduce -> global atomicMax
#pragma unroll
    for (int mi = 0; mi < 2; mi++) {
#pragma unroll
        for (int h = 0; h < 2; h++) {
            int rowl = wm * 32 + mi * 16 + h * 8 + (lane >> 2);
            float bv = -FLT_MAX; int bc = 0;
#pragma unroll
            for (int ni = 0; ni < 8; ni++) {
#pragma unroll
                for (int j = 0; j < 2; j++) {
                    float v = acc[mi][ni][h * 2 + j];
                    int col = n0 + wn * 64 + ni * 8 + (lane & 3) * 2 + j;
                    if (v > bv || (v == bv && col < bc)) { bv = v; bc = col; }
                }
            }
            uint32_t u = __float_as_uint(bv);
            u = (u & 0x80000000u) ? ~u : (u | 0x80000000u);
            unsigned long long key =
                ((unsigned long long)u << 32) | (unsigned long long)(0xFFFFFFFFu - (uint32_t)bc);
#pragma unroll
            for (int m = 1; m < 4; m <<= 1) {
                unsigned long long o = shfl_xor_u64(key, m);
                if (o > key) key = o;
            }
            if ((lane & 3) == 0)
                atomicMax(&g_amax[b * MM + m0 + rowl], key);
        }
    }
}

// ---------------- K4: scatter-add weighted dropped tokens ----------------
__global__ void scatter_kernel(const float* __restrict__ tok, float* __restrict__ out_tok)
{
    int w    = (blockIdx.x * blockDim.x + threadIdx.x) >> 5;
    int lane = threadIdx.x & 31;
    if (w >= BB * MM) return;
    int b = w / MM;
    unsigned long long key = g_amax[w];
    int a = (int)(0xFFFFFFFFu - (uint32_t)(key & 0xFFFFFFFFull));
    int gi = g_drop_idx[w];
    float dsc = fmaxf(g_drop_sc[w], 0.0f);
    const float4* src = (const float4*)(tok + ((size_t)b * NN + gi) * DD);
    float* dst = out_tok + ((size_t)b * KK + a) * DD;
#pragma unroll
    for (int i = 0; i < 8; i++) {
        float4 x = src[lane + 32 * i];
        int o = (lane + 32 * i) * 4;
        atomicAdd(dst + o + 0, x.x * dsc);
        atomicAdd(dst + o + 1, x.y * dsc);
        atomicAdd(dst + o + 2, x.z * dsc);
        atomicAdd(dst + o + 3, x.w * dsc);
    }
    if (!lane) atomicAdd(&g_sacc[b * KK + a], dsc);
}

// ---------------- K5: divide by denom ----------------
__global__ void final_kernel(float* __restrict__ out_tok)
{
    int w    = (blockIdx.x * blockDim.x + threadIdx.x) >> 5;
    int lane = threadIdx.x & 31;
    if (w >= BB * KK) return;
    float denom = fmaxf(g_sacc[w], 1e-6f);
    float4* p = (float4*)(out_tok + (size_t)w * DD);
#pragma unroll
    for (int i = 0; i < 8; i++) {
        float4 x = p[lane + 32 * i];
        x.x /= denom; x.y /= denom; x.z /= denom; x.w /= denom;
        p[lane + 32 * i] = x;
    }
}

// ---------------- entry ----------------
extern "C" void kernel_launch(void* const* d_in, const int* in_sizes, int n_in,
                              void* d_out, int out_size)
{
    const float* tok    = (const float*)d_in[0];   // [B,N,D] f32
    const float* scores = (const float*)d_in[1];   // [B,N]   f32
    float* out = (float*)d_out;

    float* out_tok = out;                                   // [B,K,D]
    int write_extra = (out_size >= BB * KK * DD + 2 * BB * KK);
    float* out_idx = out + (size_t)BB * KK * DD;            // [B,K] indices (as float)
    float* out_sc  = out_idx + BB * KK;                     // [B,K] scores

    topk_kernel<<<BB, 1024>>>(scores, out_idx, out_sc, write_extra);
    prep_kernel<<<(BB * NN) / 8, 256>>>(tok);
    init_kernel<<<(BB * KK) / 8, 256>>>(tok, out_tok);
    dim3 g(MM / 128, KK / 128, BB);
    mma_argmax_kernel<<<g, 256>>>();
    scatter_kernel<<<(BB * MM) / 8, 256>>>(tok, out_tok);
    final_kernel<<<(BB * KK) / 8, 256>>>(out_tok);
}

// round 5
// speedup vs baseline: 3.1449x; 1.7174x over previous
#include <cuda_runtime.h>
#include <cuda_bf16.h>
#include <cuda_fp16.h>
#include <math.h>
#include <float.h>
#include <stdint.h>

#define BB 16
#define NN 4096
#define DD 1024
#define KK 1024
#define MM (NN - KK)   // 3072

// ---------------- device scratch (no allocations allowed) ----------------
__device__ int   g_kept_idx[BB * KK];
__device__ float g_kept_sc [BB * KK];
__device__ int   g_drop_idx[BB * MM];
__device__ float g_drop_sc [BB * MM];
__device__ float g_sacc    [BB * KK];
__device__ unsigned long long g_amax[BB * MM];   // packed (orderfloat<<32 | ~col)

// fp16 hi/lo split of (normalized * 256) gathered rows
__device__ __align__(16) __half g_Dh[(size_t)BB * MM * DD];
__device__ __align__(16) __half g_Dl[(size_t)BB * MM * DD];
__device__ __align__(16) __half g_Kh[(size_t)BB * KK * DD];
__device__ __align__(16) __half g_Kl[(size_t)BB * KK * DD];

// ---------------- PTX helpers ----------------
__device__ __forceinline__ uint32_t smem_u32(const void* p) {
    uint32_t a;
    asm("{ .reg .u64 t; cvta.to.shared.u64 t, %1; cvt.u32.u64 %0, t; }" : "=r"(a) : "l"(p));
    return a;
}
__device__ __forceinline__ void cp16(uint32_t dst, const void* src) {
    asm volatile("cp.async.cg.shared.global [%0], [%1], 16;" :: "r"(dst), "l"(src));
}
#define CP_COMMIT() asm volatile("cp.async.commit_group;" ::: "memory")
#define CP_WAIT1()  asm volatile("cp.async.wait_group 1;" ::: "memory")
#define CP_WAIT0()  asm volatile("cp.async.wait_group 0;" ::: "memory")

__device__ __forceinline__ void ldsm_x4(uint32_t* r, uint32_t addr) {
    asm volatile("ldmatrix.sync.aligned.m8n8.x4.shared.b16 {%0,%1,%2,%3}, [%4];"
        : "=r"(r[0]), "=r"(r[1]), "=r"(r[2]), "=r"(r[3]) : "r"(addr));
}
__device__ __forceinline__ void mma16816h(float* c, const uint32_t* a, uint32_t b0, uint32_t b1) {
    asm volatile(
        "mma.sync.aligned.m16n8k16.row.col.f32.f16.f16.f32 "
        "{%0,%1,%2,%3}, {%4,%5,%6,%7}, {%8,%9}, {%0,%1,%2,%3};"
        : "+f"(c[0]), "+f"(c[1]), "+f"(c[2]), "+f"(c[3])
        : "r"(a[0]), "r"(a[1]), "r"(a[2]), "r"(a[3]), "r"(b0), "r"(b1));
}
__device__ __forceinline__ unsigned long long shfl_xor_u64(unsigned long long x, int m) {
    uint32_t lo = (uint32_t)x, hi = (uint32_t)(x >> 32);
    lo = __shfl_xor_sync(0xffffffffu, lo, m);
    hi = __shfl_xor_sync(0xffffffffu, hi, m);
    return ((unsigned long long)hi << 32) | lo;
}

// ---------------- block scan helper ----------------
__device__ __forceinline__ int block_excl_scan_1024(int val, int* wsum) {
    int tid = threadIdx.x;
    int lane = tid & 31, w = tid >> 5;
    __syncthreads();
    int v = val;
#pragma unroll
    for (int off = 1; off < 32; off <<= 1) {
        int n = __shfl_up_sync(0xffffffffu, v, off);
        if (lane >= off) v += n;
    }
    if (lane == 31) wsum[w] = v;
    __syncthreads();
    if (w == 0) {
        int s = wsum[lane];
#pragma unroll
        for (int off = 1; off < 32; off <<= 1) {
            int n = __shfl_up_sync(0xffffffffu, s, off);
            if (lane >= off) s += n;
        }
        wsum[lane] = s;
    }
    __syncthreads();
    int base = (w ? wsum[w - 1] : 0);
    return base + v - val;
}

// ---------------- K1: exact top-K select (value desc, index asc ties) ------
__global__ void __launch_bounds__(1024) topk_kernel(const float* __restrict__ scores,
                                                    float* __restrict__ out_idx,
                                                    float* __restrict__ out_sc,
                                                    int write_out)
{
    const int b   = blockIdx.x;
    const int tid = threadIdx.x;

    __shared__ float sh[NN];
    __shared__ int   hist[NN];
    __shared__ float tlv[1024];
    __shared__ int   tli[1024];
    __shared__ int   wsum[32];
    __shared__ int   s_t, s_C, s_nt;

    const float* sc = scores + (size_t)b * NN;
#pragma unroll
    for (int q = 0; q < 4; q++) {
        int i = tid * 4 + q;
        sh[i]   = sc[i];
        hist[i] = 0;
    }
    if (tid == 0) s_nt = 0;
    __syncthreads();

#pragma unroll
    for (int q = 0; q < 4; q++) {
        int i = tid * 4 + q;
        float s = sh[i];
        int bkt = (int)(s * (float)NN);
        bkt = max(0, min(NN - 1, bkt));
        atomicAdd(&hist[bkt], 1);
    }
    __syncthreads();

    int lc[4]; int cnt = 0;
#pragma unroll
    for (int q = 0; q < 4; q++) {
        lc[q] = hist[NN - 1 - (tid * 4 + q)];
        cnt += lc[q];
    }
    int base = block_excl_scan_1024(cnt, wsum);
    {
        int run = 0;
#pragma unroll
        for (int q = 0; q < 4; q++) {
            int rbin  = NN - 1 - (tid * 4 + q);
            int above = base + run;
            run += lc[q];
            if (above < KK && above + lc[q] >= KK) { s_t = rbin; s_C = above; }
        }
    }
    __syncthreads();
    const int tbkt = s_t, C = s_C, need = KK - C;

#pragma unroll
    for (int q = 0; q < 4; q++) {
        int i = tid * 4 + q;
        float s = sh[i];
        int bkt = max(0, min(NN - 1, (int)(s * (float)NN)));
        if (bkt == tbkt) {
            int p = atomicAdd(&s_nt, 1);
            if (p < 1024) { tlv[p] = s; tli[p] = i; }
        }
    }
    __syncthreads();
    const int nt = min(s_nt, 1024);

    int kf[4]; int kcnt = 0;
#pragma unroll
    for (int q = 0; q < 4; q++) {
        int i = tid * 4 + q;
        float s = sh[i];
        int bkt = max(0, min(NN - 1, (int)(s * (float)NN)));
        int kept;
        if (bkt > tbkt)      kept = 1;
        else if (bkt < tbkt) kept = 0;
        else {
            int br = 0;
            for (int j = 0; j < nt; j++) {
                float ov = tlv[j]; int oi = tli[j];
                br += (ov > s) || (ov == s && oi < i);
            }
            kept = (br < need);
        }
        kf[q] = kept; kcnt += kept;
    }

    int kbase = block_excl_scan_1024(kcnt, wsum);
    int krun = 0;
#pragma unroll
    for (int q = 0; q < 4; q++) {
        int i = tid * 4 + q;
        float s = sh[i];
        if (kf[q]) {
            int kp = kbase + krun; krun++;
            g_kept_idx[b * KK + kp] = i;
            g_kept_sc [b * KK + kp] = s;
            if (write_out) {
                out_idx[b * KK + kp] = (float)i;
                out_sc [b * KK + kp] = s;
            }
        } else {
            int dp = i - (kbase + krun);
            g_drop_idx[b * MM + dp] = i;
            g_drop_sc [b * MM + dp] = s;
        }
    }
}

// ---------------- K2: gather + normalize + fp16 hi/lo split + init out ----
// Normalized rows scaled by 256 before split so the lo part stays in the
// fp16 normal range (argmax is scale-invariant).
__global__ void prep_kernel(const float* __restrict__ tok, float* __restrict__ out_tok)
{
    int w    = (blockIdx.x * blockDim.x + threadIdx.x) >> 5;
    int lane = threadIdx.x & 31;
    if (w >= BB * NN) return;

    if (lane == 0 && w < BB * MM) g_amax[w] = 0ull;

    int b, gi;
    int is_kept;
    __half *dh, *dl;
    const int half_ = BB * KK;
    if (w < half_) {
        b  = w >> 10;
        gi = g_kept_idx[w];
        dh = g_Kh + (size_t)w * DD;
        dl = g_Kl + (size_t)w * DD;
        is_kept = 1;
    } else {
        int w2 = w - half_;
        b  = w2 / MM;
        gi = g_drop_idx[w2];
        dh = g_Dh + (size_t)w2 * DD;
        dl = g_Dl + (size_t)w2 * DD;
        is_kept = 0;
    }

    const float4* src = (const float4*)(tok + ((size_t)b * NN + gi) * DD);
    float4 x[8];
    float ss = 0.f;
#pragma unroll
    for (int i = 0; i < 8; i++) {
        x[i] = src[lane + 32 * i];
        ss += x[i].x * x[i].x + x[i].y * x[i].y + x[i].z * x[i].z + x[i].w * x[i].w;
    }
#pragma unroll
    for (int o = 16; o; o >>= 1) ss += __shfl_xor_sync(0xffffffffu, ss, o);
    float inv = 256.0f / fmaxf(sqrtf(ss), 1e-12f);   // scale lift x256

    // init output for kept rows: out = tok_row * max(score,0)
    if (is_kept) {
        float ksc = fmaxf(g_kept_sc[w], 0.0f);
        float4* dst = (float4*)(out_tok + (size_t)w * DD);
#pragma unroll
        for (int i = 0; i < 8; i++) {
            float4 y = x[i];
            y.x *= ksc; y.y *= ksc; y.z *= ksc; y.w *= ksc;
            dst[lane + 32 * i] = y;
        }
        if (!lane) g_sacc[w] = ksc;
    }

#pragma unroll
    for (int i = 0; i < 8; i++) {
        float v[4] = { x[i].x * inv, x[i].y * inv, x[i].z * inv, x[i].w * inv };
        __half h[4], l[4];
#pragma unroll
        for (int q = 0; q < 4; q++) {
            h[q] = __float2half_rn(v[q]);
            l[q] = __float2half_rn(v[q] - __half2float(h[q]));
        }
        int e = (lane + 32 * i) * 4;
        *(__half2*)(dh + e)     = __half2(h[0], h[1]);
        *(__half2*)(dh + e + 2) = __half2(h[2], h[3]);
        *(__half2*)(dl + e)     = __half2(l[0], l[1]);
        *(__half2*)(dl + e + 2) = __half2(l[2], l[3]);
    }
}

// ---------------- K3: fp16 mma.sync GEMM, 3-term split fused per chunk ----
// sim = Ah*Bh + Ah*Bl + Al*Bh  (Al*Bl ~2^-22-relative, dropped).
// CTA tile 128(M) x 128(N); grid (24, 8, 16). Per d0-chunk of 32 load the
// 4 tiles once. SMEM rows padded to 80B stride -> conflict-free ldmatrix.
#define KC 32
#define ROWB 80
#define TILEB (128 * ROWB)       // 10240 bytes per tile
#define STAGEB (4 * TILEB)       // 40960 bytes per stage (Ah,Al,Bh,Bl)
#define NCHUNK (DD / KC)         // 32

__global__ void __launch_bounds__(256, 2) mma_argmax_kernel()
{
    extern __shared__ __align__(128) char smem_dyn[];
    const uint32_t sBase = smem_u32(smem_dyn);

    const int b    = blockIdx.z;
    const int m0   = blockIdx.x * 128;
    const int n0   = blockIdx.y * 128;
    const int tid  = threadIdx.x;
    const int lane = tid & 31;
    const int wid  = tid >> 5;
    const int wm   = wid & 3;       // 4 warps along M (32 rows each)
    const int wn   = wid >> 2;      // 2 warps along N (64 cols each)

    // per-thread load mapping: row = tid>>1, 32-byte half = tid&1
    const int lrow = tid >> 1;
    const int lh   = (tid & 1) * 32;

    const char* pAh = (const char*)(g_Dh + ((size_t)b * MM + m0 + lrow) * DD) + lh;
    const char* pAl = (const char*)(g_Dl + ((size_t)b * MM + m0 + lrow) * DD) + lh;
    const char* pBh = (const char*)(g_Kh + ((size_t)b * KK + n0 + lrow) * DD) + lh;
    const char* pBl = (const char*)(g_Kl + ((size_t)b * KK + n0 + lrow) * DD) + lh;
    const uint32_t dBase = sBase + (uint32_t)(lrow * ROWB + lh);

    float acc[2][8][4];
#pragma unroll
    for (int mi = 0; mi < 2; mi++)
#pragma unroll
        for (int ni = 0; ni < 8; ni++)
#pragma unroll
            for (int j = 0; j < 4; j++) acc[mi][ni][j] = 0.f;

    // ldmatrix address components (constant per thread)
    const uint32_t aRow  = (uint32_t)(wm * 32 + (lane & 15));
    const uint32_t aByte = (uint32_t)(((lane & 16) ? 16 : 0));
    const uint32_t bRow  = (uint32_t)(wn * 64 + (lane & 7) + ((lane & 16) ? 8 : 0));
    const uint32_t bByte = (uint32_t)(((lane & 8) ? 16 : 0));

    auto issue = [&](int c, int buf) {
        const int off = c * (KC * 2);       // byte offset along K
        uint32_t d = dBase + (uint32_t)(buf * STAGEB);
        cp16(d,                  pAh + off);
        cp16(d + 16,             pAh + off + 16);
        cp16(d + TILEB,          pAl + off);
        cp16(d + TILEB + 16,     pAl + off + 16);
        cp16(d + 2 * TILEB,      pBh + off);
        cp16(d + 2 * TILEB + 16, pBh + off + 16);
        cp16(d + 3 * TILEB,      pBl + off);
        cp16(d + 3 * TILEB + 16, pBl + off + 16);
    };

    issue(0, 0);
    CP_COMMIT();

    for (int c = 0; c < NCHUNK; c++) {
        const int buf = c & 1;
        if (c + 1 < NCHUNK) {
            issue(c + 1, buf ^ 1);
            CP_COMMIT();
            CP_WAIT1();
        } else {
            CP_WAIT0();
        }
        __syncthreads();

        const uint32_t stAh = sBase + (uint32_t)(buf * STAGEB);
        const uint32_t stAl = stAh + TILEB;
        const uint32_t stBh = stAh + 2 * TILEB;
        const uint32_t stBl = stAh + 3 * TILEB;

#pragma unroll
        for (int s = 0; s < 2; s++) {
            uint32_t ah[2][4], al[2][4];
#pragma unroll
            for (int mi = 0; mi < 2; mi++) {
                ldsm_x4(ah[mi], stAh + (aRow + mi * 16) * ROWB + s * 32 + aByte);
                ldsm_x4(al[mi], stAl + (aRow + mi * 16) * ROWB + s * 32 + aByte);
            }
#pragma unroll
            for (int np = 0; np < 4; np++) {
                uint32_t bh[4], bl[4];
                ldsm_x4(bh, stBh + (bRow + np * 16) * ROWB + s * 32 + bByte);
                ldsm_x4(bl, stBl + (bRow + np * 16) * ROWB + s * 32 + bByte);
#pragma unroll
                for (int mi = 0; mi < 2; mi++) {
#pragma unroll
                    for (int nj = 0; nj < 2; nj++) {
                        float* a_ = acc[mi][np * 2 + nj];
                        mma16816h(a_, ah[mi], bh[nj * 2], bh[nj * 2 + 1]);
                        mma16816h(a_, ah[mi], bl[nj * 2], bl[nj * 2 + 1]);
                        mma16816h(a_, al[mi], bh[nj * 2], bh[nj * 2 + 1]);
                    }
                }
            }
        }
        __syncthreads();
    }

    // epilogue: per-thread rows -> quad reduce -> global atomicMax
#pragma unroll
    for (int mi = 0; mi < 2; mi++) {
#pragma unroll
        for (int h = 0; h < 2; h++) {
            int rowl = wm * 32 + mi * 16 + h * 8 + (lane >> 2);
            float bv = -FLT_MAX; int bc = 0;
#pragma unroll
            for (int ni = 0; ni < 8; ni++) {
#pragma unroll
                for (int j = 0; j < 2; j++) {
                    float v = acc[mi][ni][h * 2 + j];
                    int col = n0 + wn * 64 + ni * 8 + (lane & 3) * 2 + j;
                    if (v > bv || (v == bv && col < bc)) { bv = v; bc = col; }
                }
            }
            uint32_t u = __float_as_uint(bv);
            u = (u & 0x80000000u) ? ~u : (u | 0x80000000u);
            unsigned long long key =
                ((unsigned long long)u << 32) | (unsigned long long)(0xFFFFFFFFu - (uint32_t)bc);
#pragma unroll
            for (int m = 1; m < 4; m <<= 1) {
                unsigned long long o = shfl_xor_u64(key, m);
                if (o > key) key = o;
            }
            if ((lane & 3) == 0)
                atomicMax(&g_amax[b * MM + m0 + rowl], key);
        }
    }
}

// ---------------- K4: scatter-add weighted dropped tokens (vec4 RED) ------
__global__ void scatter_kernel(const float* __restrict__ tok, float* __restrict__ out_tok)
{
    int w    = (blockIdx.x * blockDim.x + threadIdx.x) >> 5;
    int lane = threadIdx.x & 31;
    if (w >= BB * MM) return;
    int b = w / MM;
    unsigned long long key = g_amax[w];
    int a = (int)(0xFFFFFFFFu - (uint32_t)(key & 0xFFFFFFFFull));
    int gi = g_drop_idx[w];
    float dsc = fmaxf(g_drop_sc[w], 0.0f);
    const float4* src = (const float4*)(tok + ((size_t)b * NN + gi) * DD);
    float* dst = out_tok + ((size_t)b * KK + a) * DD;
#pragma unroll
    for (int i = 0; i < 8; i++) {
        float4 x = src[lane + 32 * i];
        float* p = dst + (lane + 32 * i) * 4;
        asm volatile("red.global.add.v4.f32 [%0], {%1, %2, %3, %4};"
                     :: "l"(p), "f"(x.x * dsc), "f"(x.y * dsc),
                        "f"(x.z * dsc), "f"(x.w * dsc) : "memory");
    }
    if (!lane) atomicAdd(&g_sacc[b * KK + a], dsc);
}

// ---------------- K5: divide by denom ----------------
__global__ void final_kernel(float* __restrict__ out_tok)
{
    int w    = (blockIdx.x * blockDim.x + threadIdx.x) >> 5;
    int lane = threadIdx.x & 31;
    if (w >= BB * KK) return;
    float denom = fmaxf(g_sacc[w], 1e-6f);
    float4* p = (float4*)(out_tok + (size_t)w * DD);
#pragma unroll
    for (int i = 0; i < 8; i++) {
        float4 x = p[lane + 32 * i];
        x.x /= denom; x.y /= denom; x.z /= denom; x.w /= denom;
        p[lane + 32 * i] = x;
    }
}

// ---------------- entry ----------------
extern "C" void kernel_launch(void* const* d_in, const int* in_sizes, int n_in,
                              void* d_out, int out_size)
{
    const float* tok    = (const float*)d_in[0];   // [B,N,D] f32
    const float* scores = (const float*)d_in[1];   // [B,N]   f32
    float* out = (float*)d_out;

    float* out_tok = out;                                   // [B,K,D]
    int write_extra = (out_size >= BB * KK * DD + 2 * BB * KK);
    float* out_idx = out + (size_t)BB * KK * DD;            // [B,K] indices (as float)
    float* out_sc  = out_idx + BB * KK;                     // [B,K] scores

    const int dyn_smem = 2 * STAGEB;                        // 81920
    cudaFuncSetAttribute(mma_argmax_kernel,
                         cudaFuncAttributeMaxDynamicSharedMemorySize, dyn_smem);

    topk_kernel<<<BB, 1024>>>(scores, out_idx, out_sc, write_extra);
    prep_kernel<<<(BB * NN) / 8, 256>>>(tok, out_tok);
    dim3 g(MM / 128, KK / 128, BB);
    mma_argmax_kernel<<<g, 256, dyn_smem>>>();
    scatter_kernel<<<(BB * MM) / 8, 256>>>(tok, out_tok);
    final_kernel<<<(BB * KK) / 8, 256>>>(out_tok);
}